// round 8
// baseline (speedup 1.0000x reference)
#include <cuda_runtime.h>
#include <cuda_bf16.h>
#include <cstdint>
#include <math.h>

constexpr int HDIM = 768;
constexpr int SEQ  = 256;
constexpr int NB   = 16;
constexpr int NK   = 32;
constexpr int KC   = 16;           // K elems per chunk (32B = 2x16B slots)
constexpr int NCHUNK = HDIM / KC;  // 48
constexpr int BM   = 64;
constexpr int THREADS = 256;

__device__ __nv_bfloat16 g_qh[NB * SEQ * HDIM];
__device__ __nv_bfloat16 g_ql[NB * SEQ * HDIM];
__device__ __nv_bfloat16 g_kh[NK * SEQ * HDIM];
__device__ __nv_bfloat16 g_kl[NK * SEQ * HDIM];

// smem: 640 rows x 128B. Each row holds FOUR 32B buffers; buffer q, half c
// lives at 16B slot ((2q+c) ^ (row&7)) — bijective, conflict-free.
// Tiles: Ah rows 0-63, Al 64-127, Bh 128-383, Bl 384-639.
constexpr int TILES_SZ  = 640 * 128;          // 81920
constexpr int OFF_WTAB  = TILES_SZ;
constexpr int OFF_KMF   = OFF_WTAB + 1024;
constexpr int OFF_NUM   = OFF_KMF + 1024;
constexpr int OFF_DEN   = OFF_NUM + 1024;
constexpr int OFF_WSUM  = OFF_DEN + 1024;
constexpr int SMEM_TOTAL = OFF_WSUM + 64;     // 86144

__device__ __forceinline__ uint32_t smem_u32(const void* p) {
    uint32_t a;
    asm("{ .reg .u64 t; cvta.to.shared.u64 t, %1; cvt.u32.u64 %0, t; }" : "=r"(a) : "l"(p));
    return a;
}
#define CP_ASYNC(dst, src) \
    asm volatile("cp.async.cg.shared.global [%0], [%1], 16;" :: "r"(dst), "l"(src) : "memory")
#define CP_COMMIT() asm volatile("cp.async.commit_group;" ::: "memory")
#define CP_WAIT2()  asm volatile("cp.async.wait_group 2;" ::: "memory")
#define CP_WAIT1()  asm volatile("cp.async.wait_group 1;" ::: "memory")
#define CP_WAIT0()  asm volatile("cp.async.wait_group 0;" ::: "memory")

__device__ __forceinline__ void ldsm4(uint32_t* r, uint32_t addr) {
    asm volatile("ldmatrix.sync.aligned.m8n8.x4.shared.b16 {%0,%1,%2,%3}, [%4];"
                 : "=r"(r[0]), "=r"(r[1]), "=r"(r[2]), "=r"(r[3]) : "r"(addr));
}
__device__ __forceinline__ void mma16816(float* d, const uint32_t* a, uint32_t b0, uint32_t b1) {
    asm volatile("mma.sync.aligned.m16n8k16.row.col.f32.bf16.bf16.f32 "
                 "{%0,%1,%2,%3}, {%4,%5,%6,%7}, {%8,%9}, {%0,%1,%2,%3};"
                 : "+f"(d[0]), "+f"(d[1]), "+f"(d[2]), "+f"(d[3])
                 : "r"(a[0]), "r"(a[1]), "r"(a[2]), "r"(a[3]), "r"(b0), "r"(b1));
}

// normalize + hi/lo split; block 0 also zeroes the output
__global__ void normalize_kernel(const float* __restrict__ q, const float* __restrict__ k,
                                 float* __restrict__ out) {
    int tok = blockIdx.x;
    int tid = threadIdx.x;
    if (tok == 0) { out[tid] = 0.0f; out[tid + 256] = 0.0f; }
    bool isq = tok < NB * SEQ;
    int t2 = isq ? tok : tok - NB * SEQ;
    const float* src = (isq ? q : k) + (size_t)t2 * HDIM;
    float v[3];
    float ss = 0.0f;
#pragma unroll
    for (int e = 0; e < 3; e++) { v[e] = src[tid + 256 * e]; ss += v[e] * v[e]; }
#pragma unroll
    for (int o = 16; o; o >>= 1) ss += __shfl_xor_sync(0xffffffffu, ss, o);
    __shared__ float red[8];
    __shared__ float total;
    if ((tid & 31) == 0) red[tid >> 5] = ss;
    __syncthreads();
    if (tid < 8) {
        float s = red[tid];
#pragma unroll
        for (int o = 4; o; o >>= 1) s += __shfl_xor_sync(0xffu, s, o);
        if (tid == 0) total = s;
    }
    __syncthreads();
    float inv = 1.0f / fmaxf(sqrtf(total), 1e-12f);
#pragma unroll
    for (int e = 0; e < 3; e++) {
        int idx = tid + 256 * e;
        float x = v[e] * inv;
        __nv_bfloat16 h = __float2bfloat16(x);
        __nv_bfloat16 l = __float2bfloat16(x - __bfloat162float(h));
        if (isq) {
            g_qh[(size_t)t2 * HDIM + idx] = h;
            g_ql[(size_t)t2 * HDIM + idx] = l;
        } else {
            g_kh[(size_t)t2 * HDIM + idx] = h;
            g_kl[(size_t)t2 * HDIM + idx] = l;
        }
    }
}

__global__ __launch_bounds__(THREADS, 2)
void li_hmma(const float* __restrict__ plsc, const float* __restrict__ paraw,
             const int* __restrict__ qmask, const int* __restrict__ kmask,
             float* __restrict__ out) {
    extern __shared__ __align__(128) char smem[];
    const uint32_t sb = smem_u32(smem);
    const int tid = threadIdx.x, lane = tid & 31, wid = tid >> 5;
    const int mb = blockIdx.x, jb = blockIdx.y, ib = blockIdx.z;

    float* wt   = (float*)(smem + OFF_WTAB);
    float* kf   = (float*)(smem + OFF_KMF);
    float* nums = (float*)(smem + OFF_NUM);
    float* dens = (float*)(smem + OFF_DEN);
    float* wsum = (float*)(smem + OFF_WSUM);

    const float scale = __expf(plsc[0]);
    const float ar = paraw[0];
    const float alpha = ar >= 0.0f ? ar : 0.01f * ar;
    if (tid < SEQ) {
        wt[tid] = __expf(-alpha * (float)tid);
        kf[tid] = (float)kmask[jb * SEQ + tid];
    }

    // ---- loader: 1280 16B pieces per chunk = 640 rows x 2 halves.
    // thread owns rows (tid>>1)+128j (j=0..4), half c = tid&1.
    const int aq = ib * SEQ + mb * BM;
    const int bk = jb * SEQ;
    const int c = tid & 1;
    const int sw = (tid >> 1) & 7;           // row&7 (same for all j)
    const int rl = (tid >> 1) & 63;
    const int hi = tid >> 7;                  // 0 or 1
    const __nv_bfloat16* srcj[5];
    uint32_t dstj[5];
#pragma unroll
    for (int j = 0; j < 5; j++) {
        const int row = (tid >> 1) + 128 * j;
        const int i = 2 * j + hi;            // tile index 0..9
        const __nv_bfloat16* base;
        if (i == 0)      base = g_qh + (size_t)(aq + rl) * HDIM;
        else if (i == 1) base = g_ql + (size_t)(aq + rl) * HDIM;
        else if (i < 6)  base = g_kh + (size_t)(bk + (i - 2) * 64 + rl) * HDIM;
        else             base = g_kl + (size_t)(bk + (i - 6) * 64 + rl) * HDIM;
        srcj[j] = base + c * 8;
        dstj[j] = sb + (uint32_t)row * 128u;
    }

    auto issue = [&](int it, int q) {
        const uint32_t slot = (uint32_t)((((q << 1) + c) ^ sw) << 4);
        const int ko = it * KC;
#pragma unroll
        for (int j = 0; j < 5; j++)
            CP_ASYNC(dstj[j] + slot, srcj[j] + ko);
    };

    // ---- MMA: 2(m) x 4(n) warps; warp tile 32 x 64; 3-pass bf16 split ----
    const int mw = wid >> 2, nw = wid & 3;
    const int l15 = lane & 15, lhi = lane >> 4;
    float acc[2][8][4];
#pragma unroll
    for (int im = 0; im < 2; im++)
#pragma unroll
        for (int tl = 0; tl < 8; tl++)
#pragma unroll
            for (int cc = 0; cc < 4; cc++) acc[im][tl][cc] = 0.0f;

    auto compute = [&](int q) {
        const uint32_t kb = (uint32_t)((q << 1) + lhi);   // 16B slot pre-XOR
        uint32_t ah[2][4], al[2][4];
#pragma unroll
        for (int im = 0; im < 2; im++) {
            const uint32_t ro = (uint32_t)(mw * 32 + im * 16 + l15);
            const uint32_t co = (kb ^ (ro & 7u)) << 4;
            ldsm4(ah[im], sb + ro * 128u + co);            // Ah
            ldsm4(al[im], sb + 8192u + ro * 128u + co);    // Al
        }
#pragma unroll
        for (int ng = 0; ng < 4; ng++) {
            const uint32_t ro = (uint32_t)(nw * 64 + ng * 16 + l15);
            const uint32_t co = (kb ^ (ro & 7u)) << 4;
            uint32_t bh[4], bl[4];
            ldsm4(bh, sb + 16384u + ro * 128u + co);       // Bh
            ldsm4(bl, sb + 49152u + ro * 128u + co);       // Bl
#pragma unroll
            for (int im = 0; im < 2; im++)
#pragma unroll
                for (int o = 0; o < 2; o++) {
                    const int tl = ng * 2 + o;
                    mma16816(acc[im][tl], ah[im], bh[o], bh[o + 2]);
                    mma16816(acc[im][tl], al[im], bh[o], bh[o + 2]);
                    mma16816(acc[im][tl], ah[im], bl[o], bl[o + 2]);
                }
        }
    };

    // ---- 4-stage pipeline: run 3 chunks ahead, wait_group 2, 1 barrier/chunk
    issue(0, 0); CP_COMMIT();
    issue(1, 1); CP_COMMIT();
    issue(2, 2); CP_COMMIT();
#pragma unroll 1
    for (int it = 0; it < NCHUNK; ++it) {
        if (it < NCHUNK - 2)      CP_WAIT2();
        else if (it == NCHUNK - 2) CP_WAIT1();
        else                       CP_WAIT0();
        __syncthreads();   // chunk `it` visible; buf (it+3)&3 drained pre-barrier
        if (it + 3 < NCHUNK) { issue(it + 3, (it + 3) & 3); CP_COMMIT(); }
        compute(it & 3);
    }

    // ---- epilogue: softmax (no max-sub; |logit| <= scale) + sum p*C ----
    float pn[4] = {0, 0, 0, 0}, pd[4] = {0, 0, 0, 0};
    const int colq = 2 * (lane & 3);
    const int rowq = lane >> 2;
#pragma unroll
    for (int im = 0; im < 2; im++)
#pragma unroll
        for (int hh = 0; hh < 2; hh++) {
            const int r = mw * 32 + im * 16 + hh * 8 + rowq;
            const int s = mb * BM + r;
            const int slot = im * 2 + hh;
#pragma unroll
            for (int tl = 0; tl < 8; tl++)
#pragma unroll
                for (int e = 0; e < 2; e++) {
                    const float C = acc[im][tl][hh * 2 + e];
                    const int t = nw * 64 + tl * 8 + colq + e;
                    int d = s - t; d = d < 0 ? -d : d;
                    const float ex = kf[t] * __expf(scale * wt[d] * C);
                    pd[slot] += ex;
                    pn[slot] += ex * C;
                }
        }
#pragma unroll
    for (int o = 1; o <= 2; o <<= 1)
#pragma unroll
        for (int k = 0; k < 4; k++) {
            pn[k] += __shfl_xor_sync(0xffffffffu, pn[k], o);
            pd[k] += __shfl_xor_sync(0xffffffffu, pd[k], o);
        }
    if ((lane & 3) == 0)
#pragma unroll
        for (int k = 0; k < 4; k++) {
            const int r = mw * 32 + (k >> 1) * 16 + (k & 1) * 8 + rowq;
            nums[r * 4 + nw] = pn[k];
            dens[r * 4 + nw] = pd[k];
        }
    __syncthreads();
    if (tid < 64) {
        float n = 0.0f, d = 0.0f;
#pragma unroll
        for (int w = 0; w < 4; w++) { n += nums[tid * 4 + w]; d += dens[tid * 4 + w]; }
        float pt = d > 0.0f ? n / d : 0.0f;
        pt *= (float)qmask[ib * SEQ + mb * BM + tid];
#pragma unroll
        for (int o = 16; o; o >>= 1) pt += __shfl_xor_sync(0xffffffffu, pt, o);
        if (lane == 0) wsum[tid >> 5] = pt;
    }
    __syncthreads();
    if (tid == 0) atomicAdd(&out[ib * NK + jb], wsum[0] + wsum[1]);
}

extern "C" void kernel_launch(void* const* d_in, const int* in_sizes, int n_in,
                              void* d_out, int out_size) {
    const float* q    = (const float*)d_in[0];
    const float* k    = (const float*)d_in[1];
    const float* lsc  = (const float*)d_in[2];
    const float* araw = (const float*)d_in[3];
    const int*   qm   = (const int*)d_in[4];
    const int*   km   = (const int*)d_in[5];
    float* out = (float*)d_out;

    cudaFuncSetAttribute(li_hmma, cudaFuncAttributeMaxDynamicSharedMemorySize, SMEM_TOTAL);
    normalize_kernel<<<NB * SEQ + NK * SEQ, 256>>>(q, k, out);
    li_hmma<<<dim3(SEQ / BM, NK, NB), THREADS, SMEM_TOTAL>>>(lsc, araw, qm, km, out);
}

// round 9
// speedup vs baseline: 1.1834x; 1.1834x over previous
#include <cuda_runtime.h>
#include <cuda_bf16.h>
#include <cstdint>
#include <math.h>

constexpr int HDIM = 768;
constexpr int SEQ  = 256;
constexpr int NB   = 16;
constexpr int NK   = 32;
constexpr int KC   = 32;           // K elems per chunk (64B half-row)
constexpr int NCHUNK = HDIM / KC;  // 24
constexpr int BM   = 64;
constexpr int THREADS = 256;

__device__ __nv_bfloat16 g_qh[NB * SEQ * HDIM];
__device__ __nv_bfloat16 g_ql[NB * SEQ * HDIM];
__device__ __nv_bfloat16 g_kh[NK * SEQ * HDIM];
__device__ __nv_bfloat16 g_kl[NK * SEQ * HDIM];

// smem: 640 rows x 128B; each row holds both buffers (64B halves; bit6 of the
// swizzled column = buffer). Ah rows 0-63, Al 64-127, Bh 128-383, Bl 384-639.
constexpr int TILES_SZ  = 640 * 128;
constexpr int OFF_WTAB  = TILES_SZ;
constexpr int OFF_KMF   = OFF_WTAB + 1024;
constexpr int OFF_NUM   = OFF_KMF + 1024;
constexpr int OFF_DEN   = OFF_NUM + 1024;
constexpr int OFF_WSUM  = OFF_DEN + 1024;
constexpr int SMEM_TOTAL = OFF_WSUM + 64;     // 86144

__device__ __forceinline__ uint32_t smem_u32(const void* p) {
    uint32_t a;
    asm("{ .reg .u64 t; cvta.to.shared.u64 t, %1; cvt.u32.u64 %0, t; }" : "=r"(a) : "l"(p));
    return a;
}
#define CP_ASYNC(dst, src) \
    asm volatile("cp.async.cg.shared.global [%0], [%1], 16;" :: "r"(dst), "l"(src) : "memory")
#define CP_COMMIT() asm volatile("cp.async.commit_group;" ::: "memory")
#define CP_WAIT0()  asm volatile("cp.async.wait_group 0;" ::: "memory")

__device__ __forceinline__ void ldsm4(uint32_t* r, uint32_t addr) {
    asm volatile("ldmatrix.sync.aligned.m8n8.x4.shared.b16 {%0,%1,%2,%3}, [%4];"
                 : "=r"(r[0]), "=r"(r[1]), "=r"(r[2]), "=r"(r[3]) : "r"(addr));
}
__device__ __forceinline__ void mma16816(float* d, const uint32_t* a, uint32_t b0, uint32_t b1) {
    asm volatile("mma.sync.aligned.m16n8k16.row.col.f32.bf16.bf16.f32 "
                 "{%0,%1,%2,%3}, {%4,%5,%6,%7}, {%8,%9}, {%0,%1,%2,%3};"
                 : "+f"(d[0]), "+f"(d[1]), "+f"(d[2]), "+f"(d[3])
                 : "r"(a[0]), "r"(a[1]), "r"(a[2]), "r"(a[3]), "r"(b0), "r"(b1));
}

__global__ void normalize_kernel(const float* __restrict__ q, const float* __restrict__ k,
                                 float* __restrict__ out) {
    int tok = blockIdx.x;
    int tid = threadIdx.x;
    if (tok == 0) { out[tid] = 0.0f; out[tid + 256] = 0.0f; }
    bool isq = tok < NB * SEQ;
    int t2 = isq ? tok : tok - NB * SEQ;
    const float* src = (isq ? q : k) + (size_t)t2 * HDIM;
    float v[3];
    float ss = 0.0f;
#pragma unroll
    for (int e = 0; e < 3; e++) { v[e] = src[tid + 256 * e]; ss += v[e] * v[e]; }
#pragma unroll
    for (int o = 16; o; o >>= 1) ss += __shfl_xor_sync(0xffffffffu, ss, o);
    __shared__ float red[8];
    __shared__ float total;
    if ((tid & 31) == 0) red[tid >> 5] = ss;
    __syncthreads();
    if (tid < 8) {
        float s = red[tid];
#pragma unroll
        for (int o = 4; o; o >>= 1) s += __shfl_xor_sync(0xffu, s, o);
        if (tid == 0) total = s;
    }
    __syncthreads();
    float inv = 1.0f / fmaxf(sqrtf(total), 1e-12f);
#pragma unroll
    for (int e = 0; e < 3; e++) {
        int idx = tid + 256 * e;
        float x = v[e] * inv;
        __nv_bfloat16 h = __float2bfloat16(x);
        __nv_bfloat16 l = __float2bfloat16(x - __bfloat162float(h));
        if (isq) {
            g_qh[(size_t)t2 * HDIM + idx] = h;
            g_ql[(size_t)t2 * HDIM + idx] = l;
        } else {
            g_kh[(size_t)t2 * HDIM + idx] = h;
            g_kl[(size_t)t2 * HDIM + idx] = l;
        }
    }
}

__global__ __launch_bounds__(THREADS, 2)
void li_hmma(const float* __restrict__ plsc, const float* __restrict__ paraw,
             const int* __restrict__ qmask, const int* __restrict__ kmask,
             float* __restrict__ out) {
    extern __shared__ __align__(128) char smem[];
    const uint32_t sb = smem_u32(smem);
    const int tid = threadIdx.x, lane = tid & 31, wid = tid >> 5;
    const int mb = blockIdx.x, jb = blockIdx.y, ib = blockIdx.z;

    float* wt   = (float*)(smem + OFF_WTAB);
    float* kf   = (float*)(smem + OFF_KMF);
    float* nums = (float*)(smem + OFF_NUM);
    float* dens = (float*)(smem + OFF_DEN);
    float* wsum = (float*)(smem + OFF_WSUM);

    const float scale = __expf(plsc[0]);
    const float ar = paraw[0];
    const float alpha = ar >= 0.0f ? ar : 0.01f * ar;
    if (tid < SEQ) {
        wt[tid] = __expf(-alpha * (float)tid);
        kf[tid] = (float)kmask[jb * SEQ + tid];
    }

    // ---- loader: r0 = tid>>2, f = tid&3; thread covers row r0+64i (i=0..9),
    // one 16B piece per row, per chunk.
    const int r0 = tid >> 2, f = tid & 3;
    const size_t offA = (size_t)(ib * SEQ + mb * BM + r0) * HDIM + f * 8;
    const size_t offB = (size_t)(jb * SEQ + r0) * HDIM + f * 8;
    const __nv_bfloat16* sAh = g_qh + offA;
    const __nv_bfloat16* sAl = g_ql + offA;
    const __nv_bfloat16* sBh = g_kh + offB;
    const __nv_bfloat16* sBl = g_kl + offB;
    const uint32_t dstb = sb + (uint32_t)r0 * 128u + (uint32_t)(((f ^ (r0 & 7)) & 7) << 4);

    auto issue = [&](int it, uint32_t bx) {
        const int ko = it * KC;
        CP_ASYNC((dstb ^ bx) + 0 * 8192, sAh + ko);
        CP_ASYNC((dstb ^ bx) + 1 * 8192, sAl + ko);
#pragma unroll
        for (int j = 0; j < 4; j++)
            CP_ASYNC((dstb ^ bx) + (2 + j) * 8192, sBh + j * (64 * HDIM) + ko);
#pragma unroll
        for (int j = 0; j < 4; j++)
            CP_ASYNC((dstb ^ bx) + (6 + j) * 8192, sBl + j * (64 * HDIM) + ko);
    };

    // ---- MMA: 2(m) x 4(n) warps; warp tile 32 x 64; 3-pass bf16 split ----
    // Precomputed warp-constant LDSM bases; every address is
    //   base ^ ((ks<<5)|bx)  +  compile-time immediate
    // (row-group offsets of 16/64 rows never change row&7).
    const int mw = wid >> 2, nw = wid & 3;
    const int l15 = lane & 15, lhi = lane >> 4;
    const uint32_t roA = (uint32_t)(mw * 32 + l15);
    const uint32_t roB = (uint32_t)(nw * 64 + l15);
    const uint32_t baseA = sb + roA * 128u + ((((uint32_t)lhi ^ (roA & 7u)) & 7u) << 4);
    const uint32_t baseB = sb + 16384u + roB * 128u + ((((uint32_t)lhi ^ (roB & 7u)) & 7u) << 4);

    float acc[2][8][4];
#pragma unroll
    for (int im = 0; im < 2; im++)
#pragma unroll
        for (int tl = 0; tl < 8; tl++)
#pragma unroll
            for (int cc = 0; cc < 4; cc++) acc[im][tl][cc] = 0.0f;

    auto compute = [&](uint32_t bx) {
#pragma unroll
        for (uint32_t ks = 0; ks < 2; ks++) {
            const uint32_t xc = bx | (ks << 5);
            const uint32_t xa = baseA ^ xc;       // 1 LOP3
            const uint32_t xb = baseB ^ xc;       // 1 LOP3
            uint32_t ah[2][4], al[2][4];
#pragma unroll
            for (int im = 0; im < 2; im++) {
                ldsm4(ah[im], xa + im * 2048u);            // Ah
                ldsm4(al[im], xa + 8192u + im * 2048u);    // Al
            }
#pragma unroll
            for (int ng = 0; ng < 4; ng++) {
                uint32_t bh[4], bl[4];
                ldsm4(bh, xb + ng * 2048u);                // Bh
                ldsm4(bl, xb + 32768u + ng * 2048u);       // Bl
#pragma unroll
                for (int im = 0; im < 2; im++)
#pragma unroll
                    for (int o = 0; o < 2; o++) {
                        const int tl = ng * 2 + o;
                        mma16816(acc[im][tl], ah[im], bh[o], bh[o + 2]);
                        mma16816(acc[im][tl], al[im], bh[o], bh[o + 2]);
                        mma16816(acc[im][tl], ah[im], bl[o], bl[o + 2]);
                    }
            }
        }
    };

    // ---- pipeline: half-row double buffer, ONE barrier per chunk ----
    issue(0, 0); CP_COMMIT();
#pragma unroll 1
    for (int it = 0; it < NCHUNK; ++it) {
        CP_WAIT0();
        __syncthreads();
        if (it + 1 < NCHUNK) { issue(it + 1, (uint32_t)(((it + 1) & 1) << 6)); CP_COMMIT(); }
        compute((uint32_t)((it & 1) << 6));
    }

    // ---- epilogue ----
    float pn[4] = {0, 0, 0, 0}, pd[4] = {0, 0, 0, 0};
    const int colq = 2 * (lane & 3);
    const int rowq = lane >> 2;
#pragma unroll
    for (int im = 0; im < 2; im++)
#pragma unroll
        for (int hh = 0; hh < 2; hh++) {
            const int r = mw * 32 + im * 16 + hh * 8 + rowq;
            const int s = mb * BM + r;
            const int slot = im * 2 + hh;
#pragma unroll
            for (int tl = 0; tl < 8; tl++)
#pragma unroll
                for (int e = 0; e < 2; e++) {
                    const float C = acc[im][tl][hh * 2 + e];
                    const int t = nw * 64 + tl * 8 + colq + e;
                    int d = s - t; d = d < 0 ? -d : d;
                    const float ex = kf[t] * __expf(scale * wt[d] * C);
                    pd[slot] += ex;
                    pn[slot] += ex * C;
                }
        }
#pragma unroll
    for (int o = 1; o <= 2; o <<= 1)
#pragma unroll
        for (int k = 0; k < 4; k++) {
            pn[k] += __shfl_xor_sync(0xffffffffu, pn[k], o);
            pd[k] += __shfl_xor_sync(0xffffffffu, pd[k], o);
        }
    if ((lane & 3) == 0)
#pragma unroll
        for (int k = 0; k < 4; k++) {
            const int r = mw * 32 + (k >> 1) * 16 + (k & 1) * 8 + rowq;
            nums[r * 4 + nw] = pn[k];
            dens[r * 4 + nw] = pd[k];
        }
    __syncthreads();
    if (tid < 64) {
        float n = 0.0f, d = 0.0f;
#pragma unroll
        for (int w = 0; w < 4; w++) { n += nums[tid * 4 + w]; d += dens[tid * 4 + w]; }
        float pt = d > 0.0f ? n / d : 0.0f;
        pt *= (float)qmask[ib * SEQ + mb * BM + tid];
#pragma unroll
        for (int o = 16; o; o >>= 1) pt += __shfl_xor_sync(0xffffffffu, pt, o);
        if (lane == 0) wsum[tid >> 5] = pt;
    }
    __syncthreads();
    if (tid == 0) atomicAdd(&out[ib * NK + jb], wsum[0] + wsum[1]);
}

extern "C" void kernel_launch(void* const* d_in, const int* in_sizes, int n_in,
                              void* d_out, int out_size) {
    const float* q    = (const float*)d_in[0];
    const float* k    = (const float*)d_in[1];
    const float* lsc  = (const float*)d_in[2];
    const float* araw = (const float*)d_in[3];
    const int*   qm   = (const int*)d_in[4];
    const int*   km   = (const int*)d_in[5];
    float* out = (float*)d_out;

    cudaFuncSetAttribute(li_hmma, cudaFuncAttributeMaxDynamicSharedMemorySize, SMEM_TOTAL);
    normalize_kernel<<<NB * SEQ + NK * SEQ, 256>>>(q, k, out);
    li_hmma<<<dim3(SEQ / BM, NK, NB), THREADS, SMEM_TOTAL>>>(lsc, araw, qm, km, out);
}

// round 10
// speedup vs baseline: 1.7925x; 1.5146x over previous
#include <cuda_runtime.h>
#include <cuda_fp16.h>
#include <cstdint>
#include <math.h>

constexpr int HDIM = 768;
constexpr int SEQ  = 256;
constexpr int NB   = 16;
constexpr int NK   = 32;
constexpr int KC   = 32;           // K elems per chunk (64B half-row)
constexpr int NCHUNK = HDIM / KC;  // 24
constexpr int BM   = 64;
constexpr int THREADS = 256;

// fp16 hi/lo split of normalized q; single fp16 for k
__device__ __half g_qh[NB * SEQ * HDIM];
__device__ __half g_ql[NB * SEQ * HDIM];
__device__ __half g_kh[NK * SEQ * HDIM];

// smem: 384 rows x 128B; each row holds both buffers (64B halves; bit6 of the
// swizzled column = buffer). Ah rows 0-63, Al 64-127, B 128-383.
constexpr int TILES_SZ  = 384 * 128;          // 49152
constexpr int OFF_WTAB  = TILES_SZ;
constexpr int OFF_KMF   = OFF_WTAB + 1024;
constexpr int OFF_NUM   = OFF_KMF + 1024;
constexpr int OFF_DEN   = OFF_NUM + 1024;
constexpr int OFF_WSUM  = OFF_DEN + 1024;
constexpr int SMEM_TOTAL = OFF_WSUM + 64;     // 53312

__device__ __forceinline__ uint32_t smem_u32(const void* p) {
    uint32_t a;
    asm("{ .reg .u64 t; cvta.to.shared.u64 t, %1; cvt.u32.u64 %0, t; }" : "=r"(a) : "l"(p));
    return a;
}
#define CP_ASYNC(dst, src) \
    asm volatile("cp.async.cg.shared.global [%0], [%1], 16;" :: "r"(dst), "l"(src) : "memory")
#define CP_COMMIT() asm volatile("cp.async.commit_group;" ::: "memory")
#define CP_WAIT0()  asm volatile("cp.async.wait_group 0;" ::: "memory")

__device__ __forceinline__ void ldsm4(uint32_t* r, uint32_t addr) {
    asm volatile("ldmatrix.sync.aligned.m8n8.x4.shared.b16 {%0,%1,%2,%3}, [%4];"
                 : "=r"(r[0]), "=r"(r[1]), "=r"(r[2]), "=r"(r[3]) : "r"(addr));
}
__device__ __forceinline__ void mma16816(float* d, const uint32_t* a, uint32_t b0, uint32_t b1) {
    asm volatile("mma.sync.aligned.m16n8k16.row.col.f32.f16.f16.f32 "
                 "{%0,%1,%2,%3}, {%4,%5,%6,%7}, {%8,%9}, {%0,%1,%2,%3};"
                 : "+f"(d[0]), "+f"(d[1]), "+f"(d[2]), "+f"(d[3])
                 : "r"(a[0]), "r"(a[1]), "r"(a[2]), "r"(a[3]), "r"(b0), "r"(b1));
}

__global__ void normalize_kernel(const float* __restrict__ q, const float* __restrict__ k,
                                 float* __restrict__ out) {
    int tok = blockIdx.x;
    int tid = threadIdx.x;
    if (tok == 0) { out[tid] = 0.0f; out[tid + 256] = 0.0f; }
    bool isq = tok < NB * SEQ;
    int t2 = isq ? tok : tok - NB * SEQ;
    const float* src = (isq ? q : k) + (size_t)t2 * HDIM;
    float v[3];
    float ss = 0.0f;
#pragma unroll
    for (int e = 0; e < 3; e++) { v[e] = src[tid + 256 * e]; ss += v[e] * v[e]; }
#pragma unroll
    for (int o = 16; o; o >>= 1) ss += __shfl_xor_sync(0xffffffffu, ss, o);
    __shared__ float red[8];
    __shared__ float total;
    if ((tid & 31) == 0) red[tid >> 5] = ss;
    __syncthreads();
    if (tid < 8) {
        float s = red[tid];
#pragma unroll
        for (int o = 4; o; o >>= 1) s += __shfl_xor_sync(0xffu, s, o);
        if (tid == 0) total = s;
    }
    __syncthreads();
    float inv = 1.0f / fmaxf(sqrtf(total), 1e-12f);
#pragma unroll
    for (int e = 0; e < 3; e++) {
        int idx = tid + 256 * e;
        float x = v[e] * inv;
        __half h = __float2half(x);
        if (isq) {
            g_qh[(size_t)t2 * HDIM + idx] = h;
            g_ql[(size_t)t2 * HDIM + idx] = __float2half(x - __half2float(h));
        } else {
            g_kh[(size_t)t2 * HDIM + idx] = h;
        }
    }
}

__global__ __launch_bounds__(THREADS, 2)
void li_hmma(const float* __restrict__ plsc, const float* __restrict__ paraw,
             const int* __restrict__ qmask, const int* __restrict__ kmask,
             float* __restrict__ out) {
    extern __shared__ __align__(128) char smem[];
    const uint32_t sb = smem_u32(smem);
    const int tid = threadIdx.x, lane = tid & 31, wid = tid >> 5;
    const int mb = blockIdx.x, jb = blockIdx.y, ib = blockIdx.z;

    float* wt   = (float*)(smem + OFF_WTAB);
    float* kf   = (float*)(smem + OFF_KMF);
    float* nums = (float*)(smem + OFF_NUM);
    float* dens = (float*)(smem + OFF_DEN);
    float* wsum = (float*)(smem + OFF_WSUM);

    const float scale = __expf(plsc[0]);
    const float ar = paraw[0];
    const float alpha = ar >= 0.0f ? ar : 0.01f * ar;
    if (tid < SEQ) {
        wt[tid] = __expf(-alpha * (float)tid);
        kf[tid] = (float)kmask[jb * SEQ + tid];
    }

    // ---- loader: r0 = tid>>2, f = tid&3; thread covers rows r0+64i (i=0..5),
    // one 16B piece per row per chunk. i=0 Ah, 1 Al, 2-5 B.
    const int r0 = tid >> 2, f = tid & 3;
    const size_t offA = (size_t)(ib * SEQ + mb * BM + r0) * HDIM + f * 8;
    const size_t offB = (size_t)(jb * SEQ + r0) * HDIM + f * 8;
    const __half* sAh = g_qh + offA;
    const __half* sAl = g_ql + offA;
    const __half* sBh = g_kh + offB;
    const uint32_t dstb = sb + (uint32_t)r0 * 128u + (uint32_t)(((f ^ (r0 & 7)) & 7) << 4);

    auto issue = [&](int it, uint32_t bx) {
        const int ko = it * KC;
        CP_ASYNC((dstb ^ bx) + 0 * 8192, sAh + ko);
        CP_ASYNC((dstb ^ bx) + 1 * 8192, sAl + ko);
#pragma unroll
        for (int j = 0; j < 4; j++)
            CP_ASYNC((dstb ^ bx) + (2 + j) * 8192, sBh + j * (64 * HDIM) + ko);
    };

    // ---- MMA: 2(m) x 4(n) warps; warp tile 32 x 64; fp16 2-pass ----
    const int mw = wid >> 2, nw = wid & 3;
    const int l15 = lane & 15, lhi = lane >> 4;
    const uint32_t roA = (uint32_t)(mw * 32 + l15);
    const uint32_t roB = (uint32_t)(nw * 64 + l15);
    const uint32_t baseA = sb + roA * 128u + ((((uint32_t)lhi ^ (roA & 7u)) & 7u) << 4);
    const uint32_t baseB = sb + 16384u + roB * 128u + ((((uint32_t)lhi ^ (roB & 7u)) & 7u) << 4);

    float acc[2][8][4];
#pragma unroll
    for (int im = 0; im < 2; im++)
#pragma unroll
        for (int tl = 0; tl < 8; tl++)
#pragma unroll
            for (int cc = 0; cc < 4; cc++) acc[im][tl][cc] = 0.0f;

    auto compute = [&](uint32_t bx) {
#pragma unroll
        for (uint32_t ks = 0; ks < 2; ks++) {
            const uint32_t xc = bx | (ks << 5);
            const uint32_t xa = baseA ^ xc;
            const uint32_t xb = baseB ^ xc;
            uint32_t ah[2][4], al[2][4], b[4][4];
#pragma unroll
            for (int im = 0; im < 2; im++) {
                ldsm4(ah[im], xa + im * 2048u);            // Ah
                ldsm4(al[im], xa + 8192u + im * 2048u);    // Al
            }
#pragma unroll
            for (int ng = 0; ng < 4; ng++)
                ldsm4(b[ng], xb + ng * 2048u);             // B
            // pass 1: Ah x B — 16 independent MMAs (all acc tiles distinct)
#pragma unroll
            for (int ng = 0; ng < 4; ng++)
#pragma unroll
                for (int im = 0; im < 2; im++)
#pragma unroll
                    for (int o = 0; o < 2; o++)
                        mma16816(acc[im][ng * 2 + o], ah[im], b[ng][o], b[ng][o + 2]);
            // pass 2: Al x B — again 16 independent, 16-issue RAW spacing
#pragma unroll
            for (int ng = 0; ng < 4; ng++)
#pragma unroll
                for (int im = 0; im < 2; im++)
#pragma unroll
                    for (int o = 0; o < 2; o++)
                        mma16816(acc[im][ng * 2 + o], al[im], b[ng][o], b[ng][o + 2]);
        }
    };

    // ---- pipeline: half-row double buffer, ONE barrier per chunk ----
    issue(0, 0); CP_COMMIT();
#pragma unroll 1
    for (int it = 0; it < NCHUNK; ++it) {
        CP_WAIT0();
        __syncthreads();
        if (it + 1 < NCHUNK) { issue(it + 1, (uint32_t)(((it + 1) & 1) << 6)); CP_COMMIT(); }
        compute((uint32_t)((it & 1) << 6));
    }

    // ---- epilogue: softmax (no max-sub; |logit| <= scale) + sum p*C ----
    float pn[4] = {0, 0, 0, 0}, pd[4] = {0, 0, 0, 0};
    const int colq = 2 * (lane & 3);
    const int rowq = lane >> 2;
#pragma unroll
    for (int im = 0; im < 2; im++)
#pragma unroll
        for (int hh = 0; hh < 2; hh++) {
            const int r = mw * 32 + im * 16 + hh * 8 + rowq;
            const int s = mb * BM + r;
            const int slot = im * 2 + hh;
#pragma unroll
            for (int tl = 0; tl < 8; tl++)
#pragma unroll
                for (int e = 0; e < 2; e++) {
                    const float C = acc[im][tl][hh * 2 + e];
                    const int t = nw * 64 + tl * 8 + colq + e;
                    int d = s - t; d = d < 0 ? -d : d;
                    const float ex = kf[t] * __expf(scale * wt[d] * C);
                    pd[slot] += ex;
                    pn[slot] += ex * C;
                }
        }
#pragma unroll
    for (int o = 1; o <= 2; o <<= 1)
#pragma unroll
        for (int k = 0; k < 4; k++) {
            pn[k] += __shfl_xor_sync(0xffffffffu, pn[k], o);
            pd[k] += __shfl_xor_sync(0xffffffffu, pd[k], o);
        }
    if ((lane & 3) == 0)
#pragma unroll
        for (int k = 0; k < 4; k++) {
            const int r = mw * 32 + (k >> 1) * 16 + (k & 1) * 8 + rowq;
            nums[r * 4 + nw] = pn[k];
            dens[r * 4 + nw] = pd[k];
        }
    __syncthreads();
    if (tid < 64) {
        float n = 0.0f, d = 0.0f;
#pragma unroll
        for (int w = 0; w < 4; w++) { n += nums[tid * 4 + w]; d += dens[tid * 4 + w]; }
        float pt = d > 0.0f ? n / d : 0.0f;
        pt *= (float)qmask[ib * SEQ + mb * BM + tid];
#pragma unroll
        for (int o = 16; o; o >>= 1) pt += __shfl_xor_sync(0xffffffffu, pt, o);
        if (lane == 0) wsum[tid >> 5] = pt;
    }
    __syncthreads();
    if (tid == 0) atomicAdd(&out[ib * NK + jb], wsum[0] + wsum[1]);
}

extern "C" void kernel_launch(void* const* d_in, const int* in_sizes, int n_in,
                              void* d_out, int out_size) {
    const float* q    = (const float*)d_in[0];
    const float* k    = (const float*)d_in[1];
    const float* lsc  = (const float*)d_in[2];
    const float* araw = (const float*)d_in[3];
    const int*   qm   = (const int*)d_in[4];
    const int*   km   = (const int*)d_in[5];
    float* out = (float*)d_out;

    cudaFuncSetAttribute(li_hmma, cudaFuncAttributeMaxDynamicSharedMemorySize, SMEM_TOTAL);
    normalize_kernel<<<NB * SEQ + NK * SEQ, 256>>>(q, k, out);
    li_hmma<<<dim3(SEQ / BM, NK, NB), THREADS, SMEM_TOTAL>>>(lsc, araw, qm, km, out);
}

// round 11
// speedup vs baseline: 2.7417x; 1.5296x over previous
#include <cuda_runtime.h>
#include <cuda_fp16.h>
#include <cstdint>
#include <math.h>

constexpr int HDIM = 768;
constexpr int SEQ  = 256;
constexpr int NB   = 16;
constexpr int NK   = 32;
constexpr int KC   = 32;           // K elems per chunk (64B half-row)
constexpr int NCHUNK = HDIM / KC;  // 24
constexpr int BM   = 64;
constexpr int THREADS = 256;

// fp16 normalized embeddings (single precision level, single pass)
__device__ __half g_qh[NB * SEQ * HDIM];
__device__ __half g_kh[NK * SEQ * HDIM];

// smem: 320 rows x 128B; each row holds both buffers (64B halves; bit6 of the
// swizzled column = buffer). A rows 0-63, B rows 64-319.
constexpr int TILES_SZ  = 320 * 128;          // 40960
constexpr int OFF_WTAB  = TILES_SZ;
constexpr int OFF_KMF   = OFF_WTAB + 1024;
constexpr int OFF_NUM   = OFF_KMF + 1024;
constexpr int OFF_DEN   = OFF_NUM + 1024;
constexpr int OFF_WSUM  = OFF_DEN + 1024;
constexpr int SMEM_TOTAL = OFF_WSUM + 64;     // 45120

__device__ __forceinline__ uint32_t smem_u32(const void* p) {
    uint32_t a;
    asm("{ .reg .u64 t; cvta.to.shared.u64 t, %1; cvt.u32.u64 %0, t; }" : "=r"(a) : "l"(p));
    return a;
}
#define CP_ASYNC(dst, src) \
    asm volatile("cp.async.cg.shared.global [%0], [%1], 16;" :: "r"(dst), "l"(src) : "memory")
#define CP_COMMIT() asm volatile("cp.async.commit_group;" ::: "memory")
#define CP_WAIT0()  asm volatile("cp.async.wait_group 0;" ::: "memory")

__device__ __forceinline__ void ldsm4(uint32_t* r, uint32_t addr) {
    asm volatile("ldmatrix.sync.aligned.m8n8.x4.shared.b16 {%0,%1,%2,%3}, [%4];"
                 : "=r"(r[0]), "=r"(r[1]), "=r"(r[2]), "=r"(r[3]) : "r"(addr));
}
__device__ __forceinline__ void mma16816(float* d, const uint32_t* a, uint32_t b0, uint32_t b1) {
    asm volatile("mma.sync.aligned.m16n8k16.row.col.f32.f16.f16.f32 "
                 "{%0,%1,%2,%3}, {%4,%5,%6,%7}, {%8,%9}, {%0,%1,%2,%3};"
                 : "+f"(d[0]), "+f"(d[1]), "+f"(d[2]), "+f"(d[3])
                 : "r"(a[0]), "r"(a[1]), "r"(a[2]), "r"(a[3]), "r"(b0), "r"(b1));
}

__global__ void normalize_kernel(const float* __restrict__ q, const float* __restrict__ k,
                                 float* __restrict__ out) {
    int tok = blockIdx.x;
    int tid = threadIdx.x;
    if (tok == 0) { out[tid] = 0.0f; out[tid + 256] = 0.0f; }
    bool isq = tok < NB * SEQ;
    int t2 = isq ? tok : tok - NB * SEQ;
    const float* src = (isq ? q : k) + (size_t)t2 * HDIM;
    float v[3];
    float ss = 0.0f;
#pragma unroll
    for (int e = 0; e < 3; e++) { v[e] = src[tid + 256 * e]; ss += v[e] * v[e]; }
#pragma unroll
    for (int o = 16; o; o >>= 1) ss += __shfl_xor_sync(0xffffffffu, ss, o);
    __shared__ float red[8];
    __shared__ float total;
    if ((tid & 31) == 0) red[tid >> 5] = ss;
    __syncthreads();
    if (tid < 8) {
        float s = red[tid];
#pragma unroll
        for (int o = 4; o; o >>= 1) s += __shfl_xor_sync(0xffu, s, o);
        if (tid == 0) total = s;
    }
    __syncthreads();
    float inv = 1.0f / fmaxf(sqrtf(total), 1e-12f);
#pragma unroll
    for (int e = 0; e < 3; e++) {
        int idx = tid + 256 * e;
        __half h = __float2half(v[e] * inv);
        if (isq) g_qh[(size_t)t2 * HDIM + idx] = h;
        else     g_kh[(size_t)t2 * HDIM + idx] = h;
    }
}

__global__ __launch_bounds__(THREADS, 2)
void li_hmma(const float* __restrict__ plsc, const float* __restrict__ paraw,
             const int* __restrict__ qmask, const int* __restrict__ kmask,
             float* __restrict__ out) {
    extern __shared__ __align__(128) char smem[];
    const uint32_t sb = smem_u32(smem);
    const int tid = threadIdx.x, lane = tid & 31, wid = tid >> 5;
    const int mb = blockIdx.x, jb = blockIdx.y, ib = blockIdx.z;

    float* wt   = (float*)(smem + OFF_WTAB);
    float* kf   = (float*)(smem + OFF_KMF);
    float* nums = (float*)(smem + OFF_NUM);
    float* dens = (float*)(smem + OFF_DEN);
    float* wsum = (float*)(smem + OFF_WSUM);

    const float scale = __expf(plsc[0]);
    const float ar = paraw[0];
    const float alpha = ar >= 0.0f ? ar : 0.01f * ar;
    if (tid < SEQ) {
        wt[tid] = __expf(-alpha * (float)tid);
        kf[tid] = (float)kmask[jb * SEQ + tid];
    }

    // ---- loader: r0 = tid>>2, f = tid&3; thread covers rows r0+64i (i=0..4),
    // one 16B piece per row per chunk. i=0 A, 1-4 B.
    const int r0 = tid >> 2, f = tid & 3;
    const size_t offA = (size_t)(ib * SEQ + mb * BM + r0) * HDIM + f * 8;
    const size_t offB = (size_t)(jb * SEQ + r0) * HDIM + f * 8;
    const __half* sA = g_qh + offA;
    const __half* sB = g_kh + offB;
    const uint32_t dstb = sb + (uint32_t)r0 * 128u + (uint32_t)(((f ^ (r0 & 7)) & 7) << 4);

    auto issue = [&](int it, uint32_t bx) {
        const int ko = it * KC;
        CP_ASYNC((dstb ^ bx), sA + ko);
#pragma unroll
        for (int j = 0; j < 4; j++)
            CP_ASYNC((dstb ^ bx) + (1 + j) * 8192, sB + j * (64 * HDIM) + ko);
    };

    // ---- MMA: 2(m) x 4(n) warps; warp tile 32 x 64; single fp16 pass ----
    const int mw = wid >> 2, nw = wid & 3;
    const int l15 = lane & 15, lhi = lane >> 4;
    const uint32_t roA = (uint32_t)(mw * 32 + l15);
    const uint32_t roB = (uint32_t)(nw * 64 + l15);
    const uint32_t baseA = sb + roA * 128u + ((((uint32_t)lhi ^ (roA & 7u)) & 7u) << 4);
    const uint32_t baseB = sb + 8192u + roB * 128u + ((((uint32_t)lhi ^ (roB & 7u)) & 7u) << 4);

    float acc[2][8][4];
#pragma unroll
    for (int im = 0; im < 2; im++)
#pragma unroll
        for (int tl = 0; tl < 8; tl++)
#pragma unroll
            for (int cc = 0; cc < 4; cc++) acc[im][tl][cc] = 0.0f;

    auto compute = [&](uint32_t bx) {
#pragma unroll
        for (uint32_t ks = 0; ks < 2; ks++) {
            const uint32_t xc = bx | (ks << 5);
            const uint32_t xa = baseA ^ xc;
            const uint32_t xb = baseB ^ xc;
            uint32_t a[2][4], b[4][4];
#pragma unroll
            for (int im = 0; im < 2; im++)
                ldsm4(a[im], xa + im * 2048u);
#pragma unroll
            for (int ng = 0; ng < 4; ng++)
                ldsm4(b[ng], xb + ng * 2048u);
            // 16 independent MMAs (all acc tiles distinct)
#pragma unroll
            for (int ng = 0; ng < 4; ng++)
#pragma unroll
                for (int im = 0; im < 2; im++)
#pragma unroll
                    for (int o = 0; o < 2; o++)
                        mma16816(acc[im][ng * 2 + o], a[im], b[ng][o], b[ng][o + 2]);
        }
    };

    // ---- pipeline: half-row double buffer, ONE barrier per chunk ----
    issue(0, 0); CP_COMMIT();
#pragma unroll 1
    for (int it = 0; it < NCHUNK; ++it) {
        CP_WAIT0();
        __syncthreads();
        if (it + 1 < NCHUNK) { issue(it + 1, (uint32_t)(((it + 1) & 1) << 6)); CP_COMMIT(); }
        compute((uint32_t)((it & 1) << 6));
    }

    // ---- epilogue: softmax (no max-sub; |logit| <= scale) + sum p*C ----
    float pn[4] = {0, 0, 0, 0}, pd[4] = {0, 0, 0, 0};
    const int colq = 2 * (lane & 3);
    const int rowq = lane >> 2;
#pragma unroll
    for (int im = 0; im < 2; im++)
#pragma unroll
        for (int hh = 0; hh < 2; hh++) {
            const int r = mw * 32 + im * 16 + hh * 8 + rowq;
            const int s = mb * BM + r;
            const int slot = im * 2 + hh;
#pragma unroll
            for (int tl = 0; tl < 8; tl++)
#pragma unroll
                for (int e = 0; e < 2; e++) {
                    const float C = acc[im][tl][hh * 2 + e];
                    const int t = nw * 64 + tl * 8 + colq + e;
                    int d = s - t; d = d < 0 ? -d : d;
                    const float ex = kf[t] * __expf(scale * wt[d] * C);
                    pd[slot] += ex;
                    pn[slot] += ex * C;
                }
        }
#pragma unroll
    for (int o = 1; o <= 2; o <<= 1)
#pragma unroll
        for (int k = 0; k < 4; k++) {
            pn[k] += __shfl_xor_sync(0xffffffffu, pn[k], o);
            pd[k] += __shfl_xor_sync(0xffffffffu, pd[k], o);
        }
    if ((lane & 3) == 0)
#pragma unroll
        for (int k = 0; k < 4; k++) {
            const int r = mw * 32 + (k >> 1) * 16 + (k & 1) * 8 + rowq;
            nums[r * 4 + nw] = pn[k];
            dens[r * 4 + nw] = pd[k];
        }
    __syncthreads();
    if (tid < 64) {
        float n = 0.0f, d = 0.0f;
#pragma unroll
        for (int w = 0; w < 4; w++) { n += nums[tid * 4 + w]; d += dens[tid * 4 + w]; }
        float pt = d > 0.0f ? n / d : 0.0f;
        pt *= (float)qmask[ib * SEQ + mb * BM + tid];
#pragma unroll
        for (int o = 16; o; o >>= 1) pt += __shfl_xor_sync(0xffffffffu, pt, o);
        if (lane == 0) wsum[tid >> 5] = pt;
    }
    __syncthreads();
    if (tid == 0) atomicAdd(&out[ib * NK + jb], wsum[0] + wsum[1]);
}

extern "C" void kernel_launch(void* const* d_in, const int* in_sizes, int n_in,
                              void* d_out, int out_size) {
    const float* q    = (const float*)d_in[0];
    const float* k    = (const float*)d_in[1];
    const float* lsc  = (const float*)d_in[2];
    const float* araw = (const float*)d_in[3];
    const int*   qm   = (const int*)d_in[4];
    const int*   km   = (const int*)d_in[5];
    float* out = (float*)d_out;

    cudaFuncSetAttribute(li_hmma, cudaFuncAttributeMaxDynamicSharedMemorySize, SMEM_TOTAL);
    normalize_kernel<<<NB * SEQ + NK * SEQ, 256>>>(q, k, out);
    li_hmma<<<dim3(SEQ / BM, NK, NB), THREADS, SMEM_TOTAL>>>(lsc, araw, qm, km, out);
}

// round 12
// speedup vs baseline: 3.1703x; 1.1563x over previous
#include <cuda_runtime.h>
#include <cuda_fp16.h>
#include <cstdint>
#include <math.h>

constexpr int HDIM = 768;
constexpr int SEQ  = 256;
constexpr int NB   = 16;
constexpr int NK   = 32;
constexpr int KC   = 64;           // K elems per chunk (full 128B row)
constexpr int NCHUNK = HDIM / KC;  // 12
constexpr int BM   = 64;
constexpr int THREADS = 256;

// fp16 normalized embeddings, single pass
__device__ __half g_qh[NB * SEQ * HDIM];
__device__ __half g_kh[NK * SEQ * HDIM];

// smem: two buffers of 320 rows x 128B (A rows 0-63, B rows 64-319), then aux
constexpr int BUFSZ    = 320 * 128;           // 40960
constexpr int OFF_AUX  = 2 * BUFSZ;           // 81920
constexpr int OFF_WTAB = OFF_AUX;
constexpr int OFF_KMF  = OFF_AUX + 1024;
constexpr int OFF_NUM  = OFF_AUX + 2048;
constexpr int OFF_DEN  = OFF_AUX + 3072;
constexpr int OFF_WSUM = OFF_AUX + 4096;
constexpr int SMEM_TOTAL = OFF_AUX + 4160;    // 86080

__device__ __forceinline__ uint32_t smem_u32(const void* p) {
    uint32_t a;
    asm("{ .reg .u64 t; cvta.to.shared.u64 t, %1; cvt.u32.u64 %0, t; }" : "=r"(a) : "l"(p));
    return a;
}
#define CP_ASYNC(dst, src) \
    asm volatile("cp.async.cg.shared.global [%0], [%1], 16;" :: "r"(dst), "l"(src) : "memory")
#define CP_COMMIT() asm volatile("cp.async.commit_group;" ::: "memory")
#define CP_WAIT0()  asm volatile("cp.async.wait_group 0;" ::: "memory")

__device__ __forceinline__ void ldsm4(uint32_t* r, uint32_t addr) {
    asm volatile("ldmatrix.sync.aligned.m8n8.x4.shared.b16 {%0,%1,%2,%3}, [%4];"
                 : "=r"(r[0]), "=r"(r[1]), "=r"(r[2]), "=r"(r[3]) : "r"(addr));
}
__device__ __forceinline__ void mma16816(float* d, const uint32_t* a, uint32_t b0, uint32_t b1) {
    asm volatile("mma.sync.aligned.m16n8k16.row.col.f32.f16.f16.f32 "
                 "{%0,%1,%2,%3}, {%4,%5,%6,%7}, {%8,%9}, {%0,%1,%2,%3};"
                 : "+f"(d[0]), "+f"(d[1]), "+f"(d[2]), "+f"(d[3])
                 : "r"(a[0]), "r"(a[1]), "r"(a[2]), "r"(a[3]), "r"(b0), "r"(b1));
}

__global__ void normalize_kernel(const float* __restrict__ q, const float* __restrict__ k,
                                 float* __restrict__ out) {
    int tok = blockIdx.x;
    int tid = threadIdx.x;
    if (tok == 0) { out[tid] = 0.0f; out[tid + 256] = 0.0f; }
    bool isq = tok < NB * SEQ;
    int t2 = isq ? tok : tok - NB * SEQ;
    const float* src = (isq ? q : k) + (size_t)t2 * HDIM;
    float v[3];
    float ss = 0.0f;
#pragma unroll
    for (int e = 0; e < 3; e++) { v[e] = src[tid + 256 * e]; ss += v[e] * v[e]; }
#pragma unroll
    for (int o = 16; o; o >>= 1) ss += __shfl_xor_sync(0xffffffffu, ss, o);
    __shared__ float red[8];
    __shared__ float total;
    if ((tid & 31) == 0) red[tid >> 5] = ss;
    __syncthreads();
    if (tid < 8) {
        float s = red[tid];
#pragma unroll
        for (int o = 4; o; o >>= 1) s += __shfl_xor_sync(0xffu, s, o);
        if (tid == 0) total = s;
    }
    __syncthreads();
    float inv = 1.0f / fmaxf(sqrtf(total), 1e-12f);
#pragma unroll
    for (int e = 0; e < 3; e++) {
        int idx = tid + 256 * e;
        __half h = __float2half(v[e] * inv);
        if (isq) g_qh[(size_t)t2 * HDIM + idx] = h;
        else     g_kh[(size_t)t2 * HDIM + idx] = h;
    }
}

__global__ __launch_bounds__(THREADS, 2)
void li_hmma(const float* __restrict__ plsc, const float* __restrict__ paraw,
             const int* __restrict__ qmask, const int* __restrict__ kmask,
             float* __restrict__ out) {
    extern __shared__ __align__(128) char smem[];
    const uint32_t sb = smem_u32(smem);
    const int tid = threadIdx.x, lane = tid & 31, wid = tid >> 5;
    const int mb = blockIdx.x, jb = blockIdx.y, ib = blockIdx.z;

    float* wt   = (float*)(smem + OFF_WTAB);
    float* kf   = (float*)(smem + OFF_KMF);
    float* nums = (float*)(smem + OFF_NUM);
    float* dens = (float*)(smem + OFF_DEN);
    float* wsum = (float*)(smem + OFF_WSUM);

    const float scale = __expf(plsc[0]);
    const float ar = paraw[0];
    const float alpha = ar >= 0.0f ? ar : 0.01f * ar;
    if (tid < SEQ) {
        wt[tid] = __expf(-alpha * (float)tid);
        kf[tid] = (float)kmask[jb * SEQ + tid];
    }

    // ---- loader: 2560 16B pieces per chunk; piece p = tid + 256j (j=0..9)
    //      -> row = (tid>>3) + 32j, f = tid&7 (constant). row&7 = r0&7 const.
    const int r0 = tid >> 3, f = tid & 7;
    const int aq = ib * SEQ + mb * BM;
    const int bk = jb * SEQ;
    const uint32_t sw = (uint32_t)(((f ^ (r0 & 7)) & 7) << 4);
    const __half* srcj[10];
    uint32_t dstj[10];
#pragma unroll
    for (int j = 0; j < 10; j++) {
        const int row = r0 + 32 * j;
        const __half* base = (row < 64) ? g_qh + (size_t)(aq + row) * HDIM
                                        : g_kh + (size_t)(bk + row - 64) * HDIM;
        srcj[j] = base + f * 8;
        dstj[j] = sb + (uint32_t)row * 128u + sw;
    }

    auto issue = [&](int it, uint32_t bo) {
        const int ko = it * KC;
#pragma unroll
        for (int j = 0; j < 10; j++)
            CP_ASYNC(dstj[j] + bo, srcj[j] + ko);
    };

    // ---- MMA: 2(m) x 4(n) warps; warp tile 32 x 64; single fp16 pass ----
    // ldsm addr = (base + buf_offset) ^ (ks<<5): kc = 2ks+lhi has disjoint
    // bits, and 16/64-row tile offsets never change row&7.
    const int mw = wid >> 2, nw = wid & 3;
    const int l15 = lane & 15, lhi = lane >> 4;
    const uint32_t roA = (uint32_t)(mw * 32 + l15);
    const uint32_t roB = (uint32_t)(64 + nw * 64 + l15);
    const uint32_t baseA = sb + roA * 128u + ((((uint32_t)lhi ^ (roA & 7u)) & 7u) << 4);
    const uint32_t baseB = sb + roB * 128u + ((((uint32_t)lhi ^ (roB & 7u)) & 7u) << 4);

    float acc[2][8][4];
#pragma unroll
    for (int im = 0; im < 2; im++)
#pragma unroll
        for (int tl = 0; tl < 8; tl++)
#pragma unroll
            for (int cc = 0; cc < 4; cc++) acc[im][tl][cc] = 0.0f;

    auto compute = [&](uint32_t bo) {
        const uint32_t bA = baseA + bo, bB = baseB + bo;
#pragma unroll
        for (uint32_t ks = 0; ks < 4; ks++) {
            const uint32_t xa = bA ^ (ks << 5);
            const uint32_t xb = bB ^ (ks << 5);
            uint32_t a[2][4], b[4][4];
#pragma unroll
            for (int im = 0; im < 2; im++)
                ldsm4(a[im], xa + im * 2048u);
#pragma unroll
            for (int ng = 0; ng < 4; ng++)
                ldsm4(b[ng], xb + ng * 2048u);
            // 16 independent MMAs (all acc tiles distinct)
#pragma unroll
            for (int ng = 0; ng < 4; ng++)
#pragma unroll
                for (int im = 0; im < 2; im++)
#pragma unroll
                    for (int o = 0; o < 2; o++)
                        mma16816(acc[im][ng * 2 + o], a[im], b[ng][o], b[ng][o + 2]);
        }
    };

    // ---- pipeline: double buffer, ONE barrier per chunk ----
    issue(0, 0); CP_COMMIT();
#pragma unroll 1
    for (int it = 0; it < NCHUNK; ++it) {
        CP_WAIT0();
        __syncthreads();
        if (it + 1 < NCHUNK) { issue(it + 1, ((it + 1) & 1) ? BUFSZ : 0u); CP_COMMIT(); }
        compute((it & 1) ? BUFSZ : 0u);
    }

    // ---- epilogue: softmax (no max-sub; |logit| <= scale) + sum p*C ----
    float pn[4] = {0, 0, 0, 0}, pd[4] = {0, 0, 0, 0};
    const int colq = 2 * (lane & 3);
    const int rowq = lane >> 2;
#pragma unroll
    for (int im = 0; im < 2; im++)
#pragma unroll
        for (int hh = 0; hh < 2; hh++) {
            const int r = mw * 32 + im * 16 + hh * 8 + rowq;
            const int s = mb * BM + r;
            const int slot = im * 2 + hh;
#pragma unroll
            for (int tl = 0; tl < 8; tl++)
#pragma unroll
                for (int e = 0; e < 2; e++) {
                    const float C = acc[im][tl][hh * 2 + e];
                    const int t = nw * 64 + tl * 8 + colq + e;
                    int d = s - t; d = d < 0 ? -d : d;
                    const float ex = kf[t] * __expf(scale * wt[d] * C);
                    pd[slot] += ex;
                    pn[slot] += ex * C;
                }
        }
#pragma unroll
    for (int o = 1; o <= 2; o <<= 1)
#pragma unroll
        for (int k = 0; k < 4; k++) {
            pn[k] += __shfl_xor_sync(0xffffffffu, pn[k], o);
            pd[k] += __shfl_xor_sync(0xffffffffu, pd[k], o);
        }
    if ((lane & 3) == 0)
#pragma unroll
        for (int k = 0; k < 4; k++) {
            const int r = mw * 32 + (k >> 1) * 16 + (k & 1) * 8 + rowq;
            nums[r * 4 + nw] = pn[k];
            dens[r * 4 + nw] = pd[k];
        }
    __syncthreads();
    if (tid < 64) {
        float n = 0.0f, d = 0.0f;
#pragma unroll
        for (int w = 0; w < 4; w++) { n += nums[tid * 4 + w]; d += dens[tid * 4 + w]; }
        float pt = d > 0.0f ? n / d : 0.0f;
        pt *= (float)qmask[ib * SEQ + mb * BM + tid];
#pragma unroll
        for (int o = 16; o; o >>= 1) pt += __shfl_xor_sync(0xffffffffu, pt, o);
        if (lane == 0) wsum[tid >> 5] = pt;
    }
    __syncthreads();
    if (tid == 0) atomicAdd(&out[ib * NK + jb], wsum[0] + wsum[1]);
}

extern "C" void kernel_launch(void* const* d_in, const int* in_sizes, int n_in,
                              void* d_out, int out_size) {
    const float* q    = (const float*)d_in[0];
    const float* k    = (const float*)d_in[1];
    const float* lsc  = (const float*)d_in[2];
    const float* araw = (const float*)d_in[3];
    const int*   qm   = (const int*)d_in[4];
    const int*   km   = (const int*)d_in[5];
    float* out = (float*)d_out;

    cudaFuncSetAttribute(li_hmma, cudaFuncAttributeMaxDynamicSharedMemorySize, SMEM_TOTAL);
    normalize_kernel<<<NB * SEQ + NK * SEQ, 256>>>(q, k, out);
    li_hmma<<<dim3(SEQ / BM, NK, NB), THREADS, SMEM_TOTAL>>>(lsc, araw, qm, km, out);
}

// round 13
// speedup vs baseline: 3.5628x; 1.1238x over previous
#include <cuda_runtime.h>
#include <cuda.h>
#include <cuda_fp16.h>
#include <cstdint>
#include <math.h>

constexpr int HDIM = 768;
constexpr int SEQ  = 256;
constexpr int NB   = 16;
constexpr int NK   = 32;
constexpr int KC   = 64;           // K elems per chunk (full 128B row)
constexpr int NCHUNK = HDIM / KC;  // 12
constexpr int BM   = 64;
constexpr int THREADS = 256;

// fp16 normalized embeddings, single pass
__device__ __half g_qh[NB * SEQ * HDIM];
__device__ __half g_kh[NK * SEQ * HDIM];

// smem: two buffers of 320 rows x 128B (A rows 0-63, B rows 64-319), then aux
constexpr int BUFSZ    = 320 * 128;           // 40960
constexpr int OFF_AUX  = 2 * BUFSZ;           // 81920
constexpr int OFF_WTAB = OFF_AUX;             // 256 f32 (scale folded in)
constexpr int OFF_KMF  = OFF_AUX + 1024;      // 256 f32
constexpr int OFF_NUM  = OFF_AUX + 2048;      // 64*4 f32
constexpr int OFF_DEN  = OFF_AUX + 3072;      // 64*4 f32
constexpr int OFF_WSUM = OFF_AUX + 4096;      // 2 f32
constexpr int OFF_MBAR = OFF_AUX + 4160;      // 2 x 8B mbarriers
constexpr int SMEM_TOTAL = OFF_AUX + 4224;    // 86144

__device__ __forceinline__ uint32_t smem_u32(const void* p) {
    uint32_t a;
    asm("{ .reg .u64 t; cvta.to.shared.u64 t, %1; cvt.u32.u64 %0, t; }" : "=r"(a) : "l"(p));
    return a;
}
#define MBAR_INIT(a, c) \
    asm volatile("mbarrier.init.shared.b64 [%0], %1;" :: "r"(a), "r"(c) : "memory")
#define MBAR_EXPECT_TX(a, bytes) \
    asm volatile("mbarrier.arrive.expect_tx.shared.b64 _, [%0], %1;" :: "r"(a), "r"(bytes) : "memory")
#define MBAR_WAIT(mbar_addr, phase) do {                                                      \
    uint32_t _m = (uint32_t)(mbar_addr), _p = (uint32_t)(phase), _d;                          \
    asm volatile("{\n\t.reg .pred p;\n\t"                                                     \
        "mbarrier.try_wait.parity.acquire.cta.shared::cta.b64 p, [%1], %2;\n\t"               \
        "selp.b32 %0, 1, 0, p;\n\t}" : "=r"(_d) : "r"(_m), "r"(_p) : "memory");               \
    if (!_d) {                                                                                \
        asm volatile("{\n\t.reg .pred P1;\n\tWL_%=:\n\t"                                      \
            "mbarrier.try_wait.parity.acquire.cta.shared::cta.b64 P1, [%0], %1, 0x989680;\n\t"\
            "@P1 bra.uni WD_%=;\n\tbra.uni WL_%=;\n\tWD_%=:\n\t}"                             \
            :: "r"(_m), "r"(_p) : "memory");                                                  \
    }                                                                                         \
} while (0)
#define TMA_LOAD_2D(smem_addr, tmap, cx, cy, mbar) \
    asm volatile("cp.async.bulk.tensor.2d.shared::cta.global.tile.mbarrier::complete_tx::bytes " \
                 "[%0], [%1, {%2, %3}], [%4];" \
                 :: "r"((uint32_t)(smem_addr)), "l"(tmap), "r"((int32_t)(cx)), "r"((int32_t)(cy)), \
                    "r"((uint32_t)(mbar)) : "memory")

__device__ __forceinline__ void ldsm4(uint32_t* r, uint32_t addr) {
    asm volatile("ldmatrix.sync.aligned.m8n8.x4.shared.b16 {%0,%1,%2,%3}, [%4];"
                 : "=r"(r[0]), "=r"(r[1]), "=r"(r[2]), "=r"(r[3]) : "r"(addr));
}
__device__ __forceinline__ void mma16816(float* d, const uint32_t* a, uint32_t b0, uint32_t b1) {
    asm volatile("mma.sync.aligned.m16n8k16.row.col.f32.f16.f16.f32 "
                 "{%0,%1,%2,%3}, {%4,%5,%6,%7}, {%8,%9}, {%0,%1,%2,%3};"
                 : "+f"(d[0]), "+f"(d[1]), "+f"(d[2]), "+f"(d[3])
                 : "r"(a[0]), "r"(a[1]), "r"(a[2]), "r"(a[3]), "r"(b0), "r"(b1));
}

__global__ void normalize_kernel(const float* __restrict__ q, const float* __restrict__ k,
                                 float* __restrict__ out) {
    int tok = blockIdx.x;
    int tid = threadIdx.x;
    if (tok == 0) { out[tid] = 0.0f; out[tid + 256] = 0.0f; }
    bool isq = tok < NB * SEQ;
    int t2 = isq ? tok : tok - NB * SEQ;
    const float* src = (isq ? q : k) + (size_t)t2 * HDIM;
    float v[3];
    float ss = 0.0f;
#pragma unroll
    for (int e = 0; e < 3; e++) { v[e] = src[tid + 256 * e]; ss += v[e] * v[e]; }
#pragma unroll
    for (int o = 16; o; o >>= 1) ss += __shfl_xor_sync(0xffffffffu, ss, o);
    __shared__ float red[8];
    __shared__ float total;
    if ((tid & 31) == 0) red[tid >> 5] = ss;
    __syncthreads();
    if (tid < 8) {
        float s = red[tid];
#pragma unroll
        for (int o = 4; o; o >>= 1) s += __shfl_xor_sync(0xffu, s, o);
        if (tid == 0) total = s;
    }
    __syncthreads();
    float inv = 1.0f / fmaxf(sqrtf(total), 1e-12f);
#pragma unroll
    for (int e = 0; e < 3; e++) {
        int idx = tid + 256 * e;
        __half h = __float2half(v[e] * inv);
        if (isq) g_qh[(size_t)t2 * HDIM + idx] = h;
        else     g_kh[(size_t)t2 * HDIM + idx] = h;
    }
}

__global__ __launch_bounds__(THREADS, 2)
void li_hmma(const __grid_constant__ CUtensorMap tmA,
             const __grid_constant__ CUtensorMap tmB,
             const float* __restrict__ plsc, const float* __restrict__ paraw,
             const int* __restrict__ qmask, const int* __restrict__ kmask,
             float* __restrict__ out) {
    extern __shared__ __align__(1024) char smem[];
    const uint32_t sb = smem_u32(smem);
    const int tid = threadIdx.x, lane = tid & 31, wid = tid >> 5;
    const int mb = blockIdx.x, jb = blockIdx.y, ib = blockIdx.z;

    float* wt   = (float*)(smem + OFF_WTAB);
    float* kf   = (float*)(smem + OFF_KMF);
    float* nums = (float*)(smem + OFF_NUM);
    float* dens = (float*)(smem + OFF_DEN);
    float* wsum = (float*)(smem + OFF_WSUM);
    const uint32_t mb0 = sb + OFF_MBAR, mb1 = sb + OFF_MBAR + 8;

    const float scale = __expf(plsc[0]);
    const float ar = paraw[0];
    const float alpha = ar >= 0.0f ? ar : 0.01f * ar;
    if (tid < SEQ) {
        wt[tid] = scale * __expf(-alpha * (float)tid);   // scale folded in
        kf[tid] = (float)kmask[jb * SEQ + tid];
    }
    if (tid == 0) { MBAR_INIT(mb0, 1); MBAR_INIT(mb1, 1); }
    __syncthreads();

    const int aq = ib * SEQ + mb * BM;   // A row origin
    const int bk = jb * SEQ;             // B row origin

    // ---- first chunk: 2 TMA loads into buf0 ----
    if (tid == 0) {
        MBAR_EXPECT_TX(mb0, (uint32_t)BUFSZ);
        TMA_LOAD_2D(sb,         &tmA, 0, aq, mb0);   // A: 64 rows
        TMA_LOAD_2D(sb + 8192,  &tmB, 0, bk, mb0);   // B: 256 rows
    }

    // ---- MMA: 2(m) x 4(n) warps; warp tile 32 x 64; single fp16 pass ----
    const int mw = wid >> 2, nw = wid & 3;
    const int l15 = lane & 15, lhi = lane >> 4;
    const uint32_t roA = (uint32_t)(mw * 32 + l15);
    const uint32_t roB = (uint32_t)(64 + nw * 64 + l15);
    const uint32_t baseA = sb + roA * 128u + ((((uint32_t)lhi ^ (roA & 7u)) & 7u) << 4);
    const uint32_t baseB = sb + roB * 128u + ((((uint32_t)lhi ^ (roB & 7u)) & 7u) << 4);

    float acc[2][8][4];
#pragma unroll
    for (int im = 0; im < 2; im++)
#pragma unroll
        for (int tl = 0; tl < 8; tl++)
#pragma unroll
            for (int cc = 0; cc < 4; cc++) acc[im][tl][cc] = 0.0f;

    auto compute = [&](uint32_t bo) {
        const uint32_t bA = baseA + bo, bB = baseB + bo;
#pragma unroll
        for (uint32_t ks = 0; ks < 4; ks++) {
            const uint32_t xa = bA ^ (ks << 5);
            const uint32_t xb = bB ^ (ks << 5);
            uint32_t a[2][4], b[4][4];
#pragma unroll
            for (int im = 0; im < 2; im++)
                ldsm4(a[im], xa + im * 2048u);
#pragma unroll
            for (int ng = 0; ng < 4; ng++)
                ldsm4(b[ng], xb + ng * 2048u);
#pragma unroll
            for (int ng = 0; ng < 4; ng++)
#pragma unroll
                for (int im = 0; im < 2; im++)
#pragma unroll
                    for (int o = 0; o < 2; o++)
                        mma16816(acc[im][ng * 2 + o], a[im], b[ng][o], b[ng][o + 2]);
        }
    };

    // ---- pipeline: double buffer, one mbar-wait + one barrier per chunk ----
#pragma unroll 1
    for (int it = 0; it < NCHUNK; ++it) {
        MBAR_WAIT((it & 1) ? mb1 : mb0, (it >> 1) & 1);
        __syncthreads();   // all warps past wait; compute(it-1) drained
        if (it + 1 < NCHUNK && tid == 0) {
            const uint32_t m = ((it + 1) & 1) ? mb1 : mb0;
            const uint32_t dst = sb + (((it + 1) & 1) ? (uint32_t)BUFSZ : 0u);
            MBAR_EXPECT_TX(m, (uint32_t)BUFSZ);
            TMA_LOAD_2D(dst,        &tmA, (it + 1) * KC, aq, m);
            TMA_LOAD_2D(dst + 8192, &tmB, (it + 1) * KC, bk, m);
        }
        compute((it & 1) ? (uint32_t)BUFSZ : 0u);
    }

    // ---- epilogue: softmax (no max-sub; |logit| <= scale) + sum p*C ----
    float pn[4] = {0, 0, 0, 0}, pd[4] = {0, 0, 0, 0};
    const int colq = 2 * (lane & 3);
    const int rowq = lane >> 2;
#pragma unroll
    for (int im = 0; im < 2; im++)
#pragma unroll
        for (int hh = 0; hh < 2; hh++) {
            const int r = mw * 32 + im * 16 + hh * 8 + rowq;
            const int s = mb * BM + r;
            const int slot = im * 2 + hh;
#pragma unroll
            for (int tl = 0; tl < 8; tl++)
#pragma unroll
                for (int e = 0; e < 2; e++) {
                    const float C = acc[im][tl][hh * 2 + e];
                    const int t = nw * 64 + tl * 8 + colq + e;
                    int d = s - t; d = d < 0 ? -d : d;
                    const float ex = kf[t] * __expf(wt[d] * C);
                    pd[slot] += ex;
                    pn[slot] += ex * C;
                }
        }
#pragma unroll
    for (int o = 1; o <= 2; o <<= 1)
#pragma unroll
        for (int k = 0; k < 4; k++) {
            pn[k] += __shfl_xor_sync(0xffffffffu, pn[k], o);
            pd[k] += __shfl_xor_sync(0xffffffffu, pd[k], o);
        }
    if ((lane & 3) == 0)
#pragma unroll
        for (int k = 0; k < 4; k++) {
            const int r = mw * 32 + (k >> 1) * 16 + (k & 1) * 8 + rowq;
            nums[r * 4 + nw] = pn[k];
            dens[r * 4 + nw] = pd[k];
        }
    __syncthreads();
    if (tid < 64) {
        float n = 0.0f, d = 0.0f;
#pragma unroll
        for (int w = 0; w < 4; w++) { n += nums[tid * 4 + w]; d += dens[tid * 4 + w]; }
        float pt = d > 0.0f ? n / d : 0.0f;
        pt *= (float)qmask[ib * SEQ + mb * BM + tid];
#pragma unroll
        for (int o = 16; o; o >>= 1) pt += __shfl_xor_sync(0xffffffffu, pt, o);
        if (lane == 0) wsum[tid >> 5] = pt;
    }
    __syncthreads();
    if (tid == 0) atomicAdd(&out[ib * NK + jb], wsum[0] + wsum[1]);
}

typedef CUresult (*EncodeFn)(CUtensorMap*, CUtensorMapDataType, cuuint32_t, void*,
                             const cuuint64_t*, const cuuint64_t*, const cuuint32_t*,
                             const cuuint32_t*, CUtensorMapInterleave, CUtensorMapSwizzle,
                             CUtensorMapL2promotion, CUtensorMapFloatOOBfill);

extern "C" void kernel_launch(void* const* d_in, const int* in_sizes, int n_in,
                              void* d_out, int out_size) {
    const float* q    = (const float*)d_in[0];
    const float* k    = (const float*)d_in[1];
    const float* lsc  = (const float*)d_in[2];
    const float* araw = (const float*)d_in[3];
    const int*   qm   = (const int*)d_in[4];
    const int*   km   = (const int*)d_in[5];
    float* out = (float*)d_out;

    // build TMA descriptors (deterministic, host-side, no allocation)
    void* qptr = nullptr; void* kptr = nullptr;
    cudaGetSymbolAddress(&qptr, g_qh);
    cudaGetSymbolAddress(&kptr, g_kh);
    EncodeFn enc = nullptr;
    cudaDriverEntryPointQueryResult qr;
#if CUDART_VERSION >= 12050
    cudaGetDriverEntryPointByVersion("cuTensorMapEncodeTiled", (void**)&enc, 12000,
                                     cudaEnableDefault, &qr);
#else
    cudaGetDriverEntryPoint("cuTensorMapEncodeTiled", (void**)&enc, cudaEnableDefault, &qr);
#endif
    CUtensorMap tmA, tmB;
    cuuint64_t gdA[2] = {(cuuint64_t)HDIM, (cuuint64_t)NB * SEQ};
    cuuint64_t gdB[2] = {(cuuint64_t)HDIM, (cuuint64_t)NK * SEQ};
    cuuint64_t gs[1]  = {(cuuint64_t)HDIM * 2};
    cuuint32_t boxA[2] = {64, 64}, boxB[2] = {64, 256}, es[2] = {1, 1};
    enc(&tmA, CU_TENSOR_MAP_DATA_TYPE_FLOAT16, 2, qptr, gdA, gs, boxA, es,
        CU_TENSOR_MAP_INTERLEAVE_NONE, CU_TENSOR_MAP_SWIZZLE_128B,
        CU_TENSOR_MAP_L2_PROMOTION_L2_128B, CU_TENSOR_MAP_FLOAT_OOB_FILL_NONE);
    enc(&tmB, CU_TENSOR_MAP_DATA_TYPE_FLOAT16, 2, kptr, gdB, gs, boxB, es,
        CU_TENSOR_MAP_INTERLEAVE_NONE, CU_TENSOR_MAP_SWIZZLE_128B,
        CU_TENSOR_MAP_L2_PROMOTION_L2_128B, CU_TENSOR_MAP_FLOAT_OOB_FILL_NONE);

    cudaFuncSetAttribute(li_hmma, cudaFuncAttributeMaxDynamicSharedMemorySize, SMEM_TOTAL);
    normalize_kernel<<<NB * SEQ + NK * SEQ, 256>>>(q, k, out);
    li_hmma<<<dim3(SEQ / BM, NK, NB), THREADS, SMEM_TOTAL>>>(tmA, tmB, lsc, araw, qm, km, out);
}